// round 3
// baseline (speedup 1.0000x reference)
#include <cuda_runtime.h>
#include <math.h>

#define E 2048
#define NSLAB 4
#define SLABSZ 512
#define CH 64

// ---------------- static scratch ----------------
__device__ float  g_e2s[6 * E];
__device__ float  g_P2s[6 * E];
__device__ float  g_N2s[6 * E];
__device__ float4 g_m [6 * E];            // (e1, exp(e1), exp(.2 e1), 0)
__device__ float4 g_m2[6 * E];            // (e1, P1/R, N1/R, 0)
__device__ float2 g_h01[6 * E];
__device__ float2 g_h23[6 * E];
__device__ float2 g_h45[6 * E];
__device__ float  g_part[NSLAB * 36 * E]; // [slab][cd][j]
__device__ float  g_hcat[2 * E * 18];
__device__ float  g_XW[E * 32];
__device__ float  g_G1p[8 * E * 32];
__device__ float  g_YO1[E * 32];
__device__ float4 g_Z[E];

// ---------------- packed f32x2 helpers ----------------
__device__ __forceinline__ unsigned long long pack2(float x, float y) {
    unsigned long long r;
    asm("mov.b64 %0, {%1, %2};" : "=l"(r) : "f"(x), "f"(y));
    return r;
}
__device__ __forceinline__ float2 unpack2(unsigned long long v) {
    float2 r;
    asm("mov.b64 {%0, %1}, %2;" : "=f"(r.x), "=f"(r.y) : "l"(v));
    return r;
}
__device__ __forceinline__ void ffma2(unsigned long long& d,
                                      unsigned long long a, unsigned long long b) {
    asm("fma.rn.f32x2 %0, %1, %2, %0;" : "+l"(d) : "l"(a), "l"(b));
}

// ---------------- K1: per-node h, e1, e2, exp factors ----------------
__global__ void k1_prep(const float* __restrict__ x0, const float* __restrict__ x1,
                        const float* __restrict__ Wt1, const float* __restrict__ at1,
                        const float* __restrict__ Wt2, const float* __restrict__ at2)
{
    int c = blockIdx.y;                        // combo 0..5 (gat*3+head)
    int i = blockIdx.x * 256 + threadIdx.x;
    int g = c / 3, t = c % 3;
    __shared__ float sW[192];
    __shared__ float sa[12];
    const float* W = (g == 0 ? Wt1 : Wt2) + t * 192;
    const float* a = (g == 0 ? at1 : at2) + t * 12;
    if (threadIdx.x < 192) sW[threadIdx.x] = W[threadIdx.x];
    if (threadIdx.x < 12)  sa[threadIdx.x] = a[threadIdx.x];
    __syncthreads();

    const float* x = (g == 0 ? x0 : x1) + i * 32;   // batch 0
    float h[6] = {0.f, 0.f, 0.f, 0.f, 0.f, 0.f};
#pragma unroll
    for (int k = 0; k < 32; k++) {
        float xk = x[k];
#pragma unroll
        for (int d = 0; d < 6; d++) h[d] = fmaf(xk, sW[k * 6 + d], h[d]);
    }
    float e1 = 0.f, e2 = 0.f;
#pragma unroll
    for (int d = 0; d < 6; d++) {
        e1 = fmaf(h[d], sa[d], e1);
        e2 = fmaf(h[d], sa[6 + d], e2);
    }
    int gi = c * E + i;
    g_m[gi]   = make_float4(e1, __expf(e1), __expf(0.2f * e1), 0.f);
    g_e2s[gi] = e2;
    g_P2s[gi] = __expf(e2);
    g_N2s[gi] = __expf(0.2f * e2);
    g_h01[gi] = make_float2(h[0], h[1]);
    g_h23[gi] = make_float2(h[2], h[3]);
    g_h45[gi] = make_float2(h[4], h[5]);
}

// ---------------- K2: softmax row denominators (warp per row) ----------------
__global__ void __launch_bounds__(256) k2_rowsum(const float* __restrict__ adj)
{
    int warp = threadIdx.x >> 5, lane = threadIdx.x & 31;
    int r = blockIdx.x * 8 + warp;

    float4 m[6];
    float acc[6];
#pragma unroll
    for (int c = 0; c < 6; c++) { m[c] = g_m[c * E + r]; acc[c] = 0.f; }

    const float* arow = &adj[(size_t)r * E];
    for (int it = 0; it < 16; it++) {
        int j = it * 128 + lane * 4;
        float4 av = *(const float4*)&arow[j];
#pragma unroll
        for (int c = 0; c < 6; c++) {
            float4 e2v = *(const float4*)&g_e2s[c * E + j];
            float4 pv  = *(const float4*)&g_P2s[c * E + j];
            float4 nv  = *(const float4*)&g_N2s[c * E + j];
            float x, s;
            x = m[c].x + e2v.x; s = (x > 0.f) ? m[c].y * pv.x : m[c].z * nv.x;
            acc[c] = fmaf(av.x, s, acc[c]);
            x = m[c].x + e2v.y; s = (x > 0.f) ? m[c].y * pv.y : m[c].z * nv.y;
            acc[c] = fmaf(av.y, s, acc[c]);
            x = m[c].x + e2v.z; s = (x > 0.f) ? m[c].y * pv.z : m[c].z * nv.z;
            acc[c] = fmaf(av.z, s, acc[c]);
            x = m[c].x + e2v.w; s = (x > 0.f) ? m[c].y * pv.w : m[c].z * nv.w;
            acc[c] = fmaf(av.w, s, acc[c]);
        }
    }

#pragma unroll
    for (int c = 0; c < 6; c++) {
        float v = acc[c];
        for (int off = 16; off; off >>= 1) v += __shfl_down_sync(0xffffffffu, v, off);
        if (lane == 0) {
            float inv = 1.0f / v;
            g_m2[c * E + r] = make_float4(m[c].x, m[c].y * inv, m[c].z * inv, 0.f);
        }
    }
}

// ---------------- K3: attention-weighted aggregation ----------------
// block: 192 threads = 6 warps; warp = combo c; lane = j-pair; j-tile 64
__global__ void __launch_bounds__(192) k3_att(const float* __restrict__ adj)
{
    __shared__ float4 s_m[6][CH];
    __shared__ float2 s_h01[6][CH], s_h23[6][CH], s_h45[6][CH];

    int tid = threadIdx.x;
    int c   = tid >> 5;
    int jp  = tid & 31;
    int jb  = blockIdx.x * 64;
    int j0  = jb + jp * 2;

    float e2a = g_e2s[c * E + j0],     e2b = g_e2s[c * E + j0 + 1];
    float Pa  = g_P2s[c * E + j0],     Pb  = g_P2s[c * E + j0 + 1];
    float Na  = g_N2s[c * E + j0],     Nb  = g_N2s[c * E + j0 + 1];

    unsigned long long a0 = 0, a1 = 0, a2 = 0;   // j0 accum (d01,d23,d45)
    unsigned long long b0 = 0, b1 = 0, b2 = 0;   // j1 accum

    int ibase0 = blockIdx.y * SLABSZ;
    for (int ch = 0; ch < SLABSZ / CH; ch++) {
        int ib = ibase0 + ch * CH;
        __syncthreads();
        for (int t = tid; t < 6 * CH; t += 192) {
            int cc = t / CH, ii = t % CH;
            int gi = cc * E + ib + ii;
            s_m[cc][ii]   = g_m2[gi];
            s_h01[cc][ii] = g_h01[gi];
            s_h23[cc][ii] = g_h23[gi];
            s_h45[cc][ii] = g_h45[gi];
        }
        __syncthreads();

        for (int ii = 0; ii < CH; ii++) {
            float2 av = *(const float2*)&adj[(size_t)(ib + ii) * E + j0];
            float4 m  = s_m[c][ii];
            float x0 = m.x + e2a;
            float w0 = ((x0 > 0.f) ? m.y : m.z) * ((x0 > 0.f) ? Pa : Na) * av.x;
            float x1 = m.x + e2b;
            float w1 = ((x1 > 0.f) ? m.y : m.z) * ((x1 > 0.f) ? Pb : Nb) * av.y;

            unsigned long long h01 = *(const unsigned long long*)&s_h01[c][ii];
            unsigned long long h23 = *(const unsigned long long*)&s_h23[c][ii];
            unsigned long long h45 = *(const unsigned long long*)&s_h45[c][ii];

            unsigned long long w0p = pack2(w0, w0);
            unsigned long long w1p = pack2(w1, w1);
            ffma2(a0, w0p, h01); ffma2(a1, w0p, h23); ffma2(a2, w0p, h45);
            ffma2(b0, w1p, h01); ffma2(b1, w1p, h23); ffma2(b2, w1p, h45);
        }
    }

    float2 d01 = unpack2(a0), d23 = unpack2(a1), d45 = unpack2(a2);
    float2 e01 = unpack2(b0), e23 = unpack2(b1), e45 = unpack2(b2);
    int base = blockIdx.y * 36 + c * 6;
    *(float2*)&g_part[(base + 0) * E + j0] = make_float2(d01.x, e01.x);
    *(float2*)&g_part[(base + 1) * E + j0] = make_float2(d01.y, e01.y);
    *(float2*)&g_part[(base + 2) * E + j0] = make_float2(d23.x, e23.x);
    *(float2*)&g_part[(base + 3) * E + j0] = make_float2(d23.y, e23.y);
    *(float2*)&g_part[(base + 4) * E + j0] = make_float2(d45.x, e45.x);
    *(float2*)&g_part[(base + 5) * E + j0] = make_float2(d45.y, e45.y);
}

// ---------------- K4: reduce slabs + ELU + head concat ----------------
__global__ void k4_reduce()
{
    int idx = blockIdx.x * 256 + threadIdx.x;   // 36*2048
    int cd = idx >> 11, j = idx & 2047;
    float s = 0.f;
#pragma unroll
    for (int sl = 0; sl < NSLAB; sl++) s += g_part[(sl * 36 + cd) * E + j];
    float v = s > 0.f ? s : expm1f(s);
    int c = cd / 6, d = cd % 6;
    int g = c / 3, dd = (c % 3) * 6 + d;
    g_hcat[g * (E * 18) + j * 18 + dd] = v;
}

// ---------------- K5: XW = [hcat_h @ Wg1 | hcat_o @ Wo1] ----------------
__global__ void k5_xw(const float* __restrict__ Wg1, const float* __restrict__ Wo1)
{
    int idx = blockIdx.x * 256 + threadIdx.x;   // 2048*32
    int j = idx >> 5, c = idx & 31;
    int g = c >> 4, cc = c & 15;
    const float* W = g ? Wo1 : Wg1;
    const float* h = &g_hcat[g * (E * 18) + j * 18];
    float s = 0.f;
#pragma unroll
    for (int k = 0; k < 18; k++) s = fmaf(h[k], W[k * 16 + cc], s);
    g_XW[idx] = s;
}

// ---------------- G1: a0 @ XW (tiled, k-split) ----------------
__global__ void __launch_bounds__(256) g1_gemm(const float* __restrict__ adj)
{
    __shared__ float As[64][33];
    __shared__ float Bs[32][32];
    int r0 = blockIdx.x * 64, k0 = blockIdx.y * 256;
    int rl = threadIdx.x >> 2, cg = (threadIdx.x & 3) * 8;
    int kc = threadIdx.x & 31, rr = threadIdx.x >> 5;

    float acc[8];
#pragma unroll
    for (int u = 0; u < 8; u++) acc[u] = 0.f;

    for (int kt = 0; kt < 8; kt++) {
        int kb = k0 + kt * 32;
#pragma unroll
        for (int p = 0; p < 8; p++)
            As[rr + p * 8][kc] = adj[(size_t)(r0 + rr + p * 8) * E + kb + kc];
#pragma unroll
        for (int p = 0; p < 4; p++)
            Bs[rr + p * 8][kc] = g_XW[(kb + rr + p * 8) * 32 + kc];
        __syncthreads();
#pragma unroll
        for (int kk = 0; kk < 32; kk++) {
            float a = As[rl][kk];
            const float4* b = (const float4*)&Bs[kk][cg];
            float4 b0 = b[0], b1 = b[1];
            acc[0] = fmaf(a, b0.x, acc[0]);
            acc[1] = fmaf(a, b0.y, acc[1]);
            acc[2] = fmaf(a, b0.z, acc[2]);
            acc[3] = fmaf(a, b0.w, acc[3]);
            acc[4] = fmaf(a, b1.x, acc[4]);
            acc[5] = fmaf(a, b1.y, acc[5]);
            acc[6] = fmaf(a, b1.z, acc[6]);
            acc[7] = fmaf(a, b1.w, acc[7]);
        }
        __syncthreads();
    }
    float* dst = &g_G1p[((size_t)blockIdx.y * E + r0 + rl) * 32 + cg];
    ((float4*)dst)[0] = make_float4(acc[0], acc[1], acc[2], acc[3]);
    ((float4*)dst)[1] = make_float4(acc[4], acc[5], acc[6], acc[7]);
}

// ---------------- G1r: reduce k-slices + bias + relu ----------------
__global__ void g1_reduce(const float* __restrict__ bg1, const float* __restrict__ bo1)
{
    int idx = blockIdx.x * 256 + threadIdx.x;   // 2048*32
    int c = idx & 31;
    float s = 0.f;
#pragma unroll
    for (int ks = 0; ks < 8; ks++) s += g_G1p[((size_t)ks * E) * 32 + idx];
    s += (c < 16) ? bg1[c] : bo1[c - 16];
    g_YO1[idx] = s > 0.f ? s : 0.f;
}

// ---------------- G2a: Z = [Y1@Wg2 | O1@Wo2] ----------------
__global__ void g2a(const float* __restrict__ Wg2, const float* __restrict__ Wo2)
{
    int j = blockIdx.x * 256 + threadIdx.x;     // 2048
    const float* y = &g_YO1[j * 32];
    float z0 = 0.f, z1 = 0.f, z2 = 0.f, z3 = 0.f;
#pragma unroll
    for (int k = 0; k < 16; k++) {
        z0 = fmaf(y[k], Wg2[k * 2 + 0], z0);
        z1 = fmaf(y[k], Wg2[k * 2 + 1], z1);
        z2 = fmaf(y[16 + k], Wo2[k * 2 + 0], z2);
        z3 = fmaf(y[16 + k], Wo2[k * 2 + 1], z3);
    }
    g_Z[j] = make_float4(z0, z1, z2, z3);
}

// ---------------- G2b: a0 @ Z + bias, log_softmax / leaky ----------------
__global__ void __launch_bounds__(256) g2b(const float* __restrict__ adj,
                                           const float* __restrict__ bg2,
                                           const float* __restrict__ bo2,
                                           float* __restrict__ out)
{
    int warp = threadIdx.x >> 5, lane = threadIdx.x & 31;
    int r = blockIdx.x * 8 + warp;
    float a0 = 0.f, a1 = 0.f, a2 = 0.f, a3 = 0.f;
    for (int q = 0; q < 64; q++) {
        int k = q * 32 + lane;
        float av = adj[(size_t)r * E + k];
        float4 z = g_Z[k];
        a0 = fmaf(av, z.x, a0);
        a1 = fmaf(av, z.y, a1);
        a2 = fmaf(av, z.z, a2);
        a3 = fmaf(av, z.w, a3);
    }
    for (int off = 16; off; off >>= 1) {
        a0 += __shfl_down_sync(0xffffffffu, a0, off);
        a1 += __shfl_down_sync(0xffffffffu, a1, off);
        a2 += __shfl_down_sync(0xffffffffu, a2, off);
        a3 += __shfl_down_sync(0xffffffffu, a3, off);
    }
    if (lane == 0) {
        float y0 = a0 + bg2[0], y1 = a1 + bg2[1];
        float m = fmaxf(y0, y1);
        float l = m + logf(expf(y0 - m) + expf(y1 - m));
        out[r * 2 + 0] = y0 - l;
        out[r * 2 + 1] = y1 - l;
        float o0 = a2 + bo2[0], o1 = a3 + bo2[1];
        out[2 * E + r * 2 + 0] = o0 > 0.f ? o0 : 0.01f * o0;
        out[2 * E + r * 2 + 1] = o1 > 0.f ? o1 : 0.01f * o1;
    }
}

// ---------------- launch ----------------
extern "C" void kernel_launch(void* const* d_in, const int* in_sizes, int n_in,
                              void* d_out, int out_size)
{
    (void)in_sizes; (void)n_in; (void)out_size;
    const float* node = (const float*)d_in[0];
    const float* uv   = (const float*)d_in[1];
    const float* adj  = (const float*)d_in[2];   // batch 0 = first E*E floats
    const float* Wt1  = (const float*)d_in[3];
    const float* at1  = (const float*)d_in[4];
    const float* Wt2  = (const float*)d_in[5];
    const float* at2  = (const float*)d_in[6];
    const float* Wg1  = (const float*)d_in[7];
    const float* bg1  = (const float*)d_in[8];
    const float* Wg2  = (const float*)d_in[9];
    const float* bg2  = (const float*)d_in[10];
    const float* Wo1  = (const float*)d_in[11];
    const float* bo1  = (const float*)d_in[12];
    const float* Wo2  = (const float*)d_in[13];
    const float* bo2  = (const float*)d_in[14];
    float* out = (float*)d_out;

    k1_prep<<<dim3(8, 6), 256>>>(node, uv, Wt1, at1, Wt2, at2);
    k2_rowsum<<<256, 256>>>(adj);
    k3_att<<<dim3(32, NSLAB), 192>>>(adj);
    k4_reduce<<<288, 256>>>();
    k5_xw<<<256, 256>>>(Wg1, Wo1);
    g1_gemm<<<dim3(32, 8), 256>>>(adj);
    g1_reduce<<<256, 256>>>(bg1, bo1);
    g2a<<<8, 256>>>(Wg2, Wo2);
    g2b<<<256, 256>>>(adj, bg2, bo2, out);
}

// round 4
// speedup vs baseline: 1.1122x; 1.1122x over previous
#include <cuda_runtime.h>
#include <math.h>

#define E 2048
#define NSLAB 16
#define SLABSZ 128
#define CH 64

// ---------------- static scratch ----------------
__device__ float  g_e2s[6 * E];
__device__ float  g_P2s[6 * E];
__device__ float  g_N2s[6 * E];
__device__ float4 g_m [6 * E];            // (e1, exp(e1), exp(.2 e1), 0)
__device__ float4 g_m2[6 * E];            // (e1, P1/R, N1/R, 0)
__device__ float2 g_h01[6 * E];
__device__ float2 g_h23[6 * E];
__device__ float2 g_h45[6 * E];
__device__ float  g_part[NSLAB * 36 * E]; // [slab][cd][j]
__device__ float  g_hcat[2 * E * 18];
__device__ float  g_XW[E * 32];
__device__ float  g_G1p[8 * E * 32];
__device__ float  g_YO1[E * 32];
__device__ float4 g_Z[E];

// ---------------- packed f32x2 helpers ----------------
__device__ __forceinline__ unsigned long long pack2(float x, float y) {
    unsigned long long r;
    asm("mov.b64 %0, {%1, %2};" : "=l"(r) : "f"(x), "f"(y));
    return r;
}
__device__ __forceinline__ float2 unpack2(unsigned long long v) {
    float2 r;
    asm("mov.b64 {%0, %1}, %2;" : "=f"(r.x), "=f"(r.y) : "l"(v));
    return r;
}
__device__ __forceinline__ void ffma2(unsigned long long& d,
                                      unsigned long long a, unsigned long long b) {
    asm("fma.rn.f32x2 %0, %1, %2, %0;" : "+l"(d) : "l"(a), "l"(b));
}
__device__ __forceinline__ unsigned long long mul2(unsigned long long a,
                                                   unsigned long long b) {
    unsigned long long r;
    asm("mul.rn.f32x2 %0, %1, %2;" : "=l"(r) : "l"(a), "l"(b));
    return r;
}

// ---------------- K1: per-node h, e1, e2, exp factors (one gat) ----------------
__global__ void k1_prep(const float* __restrict__ x, const float* __restrict__ Wt,
                        const float* __restrict__ at, int cbase)
{
    int t = blockIdx.y;                        // head 0..2
    int c = cbase + t;
    int i = blockIdx.x * 256 + threadIdx.x;
    __shared__ float sW[192];
    __shared__ float sa[12];
    const float* W = Wt + t * 192;
    const float* a = at + t * 12;
    if (threadIdx.x < 192) sW[threadIdx.x] = W[threadIdx.x];
    if (threadIdx.x < 12)  sa[threadIdx.x] = a[threadIdx.x];
    __syncthreads();

    const float* xr = x + i * 32;   // batch 0
    float h[6] = {0.f, 0.f, 0.f, 0.f, 0.f, 0.f};
#pragma unroll
    for (int k = 0; k < 32; k++) {
        float xk = xr[k];
#pragma unroll
        for (int d = 0; d < 6; d++) h[d] = fmaf(xk, sW[k * 6 + d], h[d]);
    }
    float e1 = 0.f, e2 = 0.f;
#pragma unroll
    for (int d = 0; d < 6; d++) {
        e1 = fmaf(h[d], sa[d], e1);
        e2 = fmaf(h[d], sa[6 + d], e2);
    }
    int gi = c * E + i;
    g_m[gi]   = make_float4(e1, __expf(e1), __expf(0.2f * e1), 0.f);
    g_e2s[gi] = e2;
    g_P2s[gi] = __expf(e2);
    g_N2s[gi] = __expf(0.2f * e2);
    g_h01[gi] = make_float2(h[0], h[1]);
    g_h23[gi] = make_float2(h[2], h[3]);
    g_h45[gi] = make_float2(h[4], h[5]);
}

// ---------------- K2: softmax row denominators (warp per row) ----------------
__global__ void __launch_bounds__(256) k2_rowsum(const float* __restrict__ adj)
{
    int warp = threadIdx.x >> 5, lane = threadIdx.x & 31;
    int r = blockIdx.x * 8 + warp;

    float4 m[6];
    float acc[6];
#pragma unroll
    for (int c = 0; c < 6; c++) { m[c] = g_m[c * E + r]; acc[c] = 0.f; }

    const float* arow = &adj[(size_t)r * E];
    for (int it = 0; it < 16; it++) {
        int j = it * 128 + lane * 4;
        float4 av = *(const float4*)&arow[j];
#pragma unroll
        for (int c = 0; c < 6; c++) {
            float4 e2v = *(const float4*)&g_e2s[c * E + j];
            float4 pv  = *(const float4*)&g_P2s[c * E + j];
            float4 nv  = *(const float4*)&g_N2s[c * E + j];
            float x, s;
            x = m[c].x + e2v.x; s = (x > 0.f) ? m[c].y * pv.x : m[c].z * nv.x;
            acc[c] = fmaf(av.x, s, acc[c]);
            x = m[c].x + e2v.y; s = (x > 0.f) ? m[c].y * pv.y : m[c].z * nv.y;
            acc[c] = fmaf(av.y, s, acc[c]);
            x = m[c].x + e2v.z; s = (x > 0.f) ? m[c].y * pv.z : m[c].z * nv.z;
            acc[c] = fmaf(av.z, s, acc[c]);
            x = m[c].x + e2v.w; s = (x > 0.f) ? m[c].y * pv.w : m[c].z * nv.w;
            acc[c] = fmaf(av.w, s, acc[c]);
        }
    }

#pragma unroll
    for (int c = 0; c < 6; c++) {
        float v = acc[c];
        for (int off = 16; off; off >>= 1) v += __shfl_down_sync(0xffffffffu, v, off);
        if (lane == 0) {
            float inv = 1.0f / v;
            g_m2[c * E + r] = make_float4(m[c].x, m[c].y * inv, m[c].z * inv, 0.f);
        }
    }
}

// ---------------- K3: attention-weighted aggregation ----------------
// block: 192 threads = 6 warps; warp = combo c; lane = j-pair; j-tile 64
__global__ void __launch_bounds__(192, 4) k3_att(const float* __restrict__ adj)
{
    __shared__ float4 s_m[6][CH];
    __shared__ unsigned long long s_h01[6][CH], s_h23[6][CH], s_h45[6][CH];

    int tid = threadIdx.x;
    int c   = tid >> 5;
    int jp  = tid & 31;
    int j0  = blockIdx.x * 64 + jp * 2;

    float e2a = g_e2s[c * E + j0], e2b = g_e2s[c * E + j0 + 1];
    unsigned long long ppa = pack2(g_P2s[c * E + j0],     g_N2s[c * E + j0]);
    unsigned long long ppb = pack2(g_P2s[c * E + j0 + 1], g_N2s[c * E + j0 + 1]);

    unsigned long long a0 = 0, a1 = 0, a2 = 0;   // j0 accum (d01,d23,d45)
    unsigned long long b0 = 0, b1 = 0, b2 = 0;   // j1 accum

    int ibase0 = blockIdx.y * SLABSZ;
    for (int ch = 0; ch < SLABSZ / CH; ch++) {
        int ib = ibase0 + ch * CH;
        __syncthreads();
        for (int t = tid; t < 6 * CH; t += 192) {
            int cc = t / CH, ii = t % CH;
            int gi = cc * E + ib + ii;
            s_m[cc][ii]   = g_m2[gi];
            s_h01[cc][ii] = *(const unsigned long long*)&g_h01[gi];
            s_h23[cc][ii] = *(const unsigned long long*)&g_h23[gi];
            s_h45[cc][ii] = *(const unsigned long long*)&g_h45[gi];
        }
        __syncthreads();

#pragma unroll 1
        for (int ii = 0; ii < CH; ii += 4) {
            float2 av[4];
#pragma unroll
            for (int u = 0; u < 4; u++)
                av[u] = *(const float2*)&adj[(size_t)(ib + ii + u) * E + j0];
#pragma unroll
            for (int u = 0; u < 4; u++) {
                float4 m = s_m[c][ii + u];
                unsigned long long pk = pack2(m.y, m.z);

                float x0 = m.x + e2a;
                float2 p0 = unpack2(mul2(pk, ppa));
                float w0 = (x0 > 0.f ? p0.x : p0.y) * av[u].x;

                float x1 = m.x + e2b;
                float2 p1 = unpack2(mul2(pk, ppb));
                float w1 = (x1 > 0.f ? p1.x : p1.y) * av[u].y;

                unsigned long long h01 = s_h01[c][ii + u];
                unsigned long long h23 = s_h23[c][ii + u];
                unsigned long long h45 = s_h45[c][ii + u];

                unsigned long long w0p = pack2(w0, w0);
                unsigned long long w1p = pack2(w1, w1);
                ffma2(a0, w0p, h01); ffma2(a1, w0p, h23); ffma2(a2, w0p, h45);
                ffma2(b0, w1p, h01); ffma2(b1, w1p, h23); ffma2(b2, w1p, h45);
            }
        }
    }

    float2 d01 = unpack2(a0), d23 = unpack2(a1), d45 = unpack2(a2);
    float2 e01 = unpack2(b0), e23 = unpack2(b1), e45 = unpack2(b2);
    int base = blockIdx.y * 36 + c * 6;
    *(float2*)&g_part[(base + 0) * E + j0] = make_float2(d01.x, e01.x);
    *(float2*)&g_part[(base + 1) * E + j0] = make_float2(d01.y, e01.y);
    *(float2*)&g_part[(base + 2) * E + j0] = make_float2(d23.x, e23.x);
    *(float2*)&g_part[(base + 3) * E + j0] = make_float2(d23.y, e23.y);
    *(float2*)&g_part[(base + 4) * E + j0] = make_float2(d45.x, e45.x);
    *(float2*)&g_part[(base + 5) * E + j0] = make_float2(d45.y, e45.y);
}

// ---------------- K4: reduce slabs + ELU + head concat ----------------
__global__ void k4_reduce()
{
    int idx = blockIdx.x * 256 + threadIdx.x;   // 36*2048
    int cd = idx >> 11, j = idx & 2047;
    float s = 0.f;
#pragma unroll
    for (int sl = 0; sl < NSLAB; sl++) s += g_part[(sl * 36 + cd) * E + j];
    float v = s > 0.f ? s : expm1f(s);
    int c = cd / 6, d = cd % 6;
    int g = c / 3, dd = (c % 3) * 6 + d;
    g_hcat[g * (E * 18) + j * 18 + dd] = v;
}

// ---------------- K5: XW = [hcat_h @ Wg1 | hcat_o @ Wo1] ----------------
__global__ void k5_xw(const float* __restrict__ Wg1, const float* __restrict__ Wo1)
{
    int idx = blockIdx.x * 256 + threadIdx.x;   // 2048*32
    int j = idx >> 5, c = idx & 31;
    int g = c >> 4, cc = c & 15;
    const float* W = g ? Wo1 : Wg1;
    const float* h = &g_hcat[g * (E * 18) + j * 18];
    float s = 0.f;
#pragma unroll
    for (int k = 0; k < 18; k++) s = fmaf(h[k], W[k * 16 + cc], s);
    g_XW[idx] = s;
}

// ---------------- G1: a0 @ XW (tiled, k-split) ----------------
__global__ void __launch_bounds__(256) g1_gemm(const float* __restrict__ adj)
{
    __shared__ float As[64][33];
    __shared__ float Bs[32][32];
    int r0 = blockIdx.x * 64, k0 = blockIdx.y * 256;
    int rl = threadIdx.x >> 2, cg = (threadIdx.x & 3) * 8;
    int kc = threadIdx.x & 31, rr = threadIdx.x >> 5;

    float acc[8];
#pragma unroll
    for (int u = 0; u < 8; u++) acc[u] = 0.f;

    for (int kt = 0; kt < 8; kt++) {
        int kb = k0 + kt * 32;
#pragma unroll
        for (int p = 0; p < 8; p++)
            As[rr + p * 8][kc] = adj[(size_t)(r0 + rr + p * 8) * E + kb + kc];
#pragma unroll
        for (int p = 0; p < 4; p++)
            Bs[rr + p * 8][kc] = g_XW[(kb + rr + p * 8) * 32 + kc];
        __syncthreads();
#pragma unroll
        for (int kk = 0; kk < 32; kk++) {
            float a = As[rl][kk];
            const float4* b = (const float4*)&Bs[kk][cg];
            float4 b0 = b[0], b1 = b[1];
            acc[0] = fmaf(a, b0.x, acc[0]);
            acc[1] = fmaf(a, b0.y, acc[1]);
            acc[2] = fmaf(a, b0.z, acc[2]);
            acc[3] = fmaf(a, b0.w, acc[3]);
            acc[4] = fmaf(a, b1.x, acc[4]);
            acc[5] = fmaf(a, b1.y, acc[5]);
            acc[6] = fmaf(a, b1.z, acc[6]);
            acc[7] = fmaf(a, b1.w, acc[7]);
        }
        __syncthreads();
    }
    float* dst = &g_G1p[((size_t)blockIdx.y * E + r0 + rl) * 32 + cg];
    ((float4*)dst)[0] = make_float4(acc[0], acc[1], acc[2], acc[3]);
    ((float4*)dst)[1] = make_float4(acc[4], acc[5], acc[6], acc[7]);
}

// ---------------- G1r: reduce k-slices + bias + relu ----------------
__global__ void g1_reduce(const float* __restrict__ bg1, const float* __restrict__ bo1)
{
    int idx = blockIdx.x * 256 + threadIdx.x;   // 2048*32
    int c = idx & 31;
    float s = 0.f;
#pragma unroll
    for (int ks = 0; ks < 8; ks++) s += g_G1p[((size_t)ks * E) * 32 + idx];
    s += (c < 16) ? bg1[c] : bo1[c - 16];
    g_YO1[idx] = s > 0.f ? s : 0.f;
}

// ---------------- G2a: Z = [Y1@Wg2 | O1@Wo2] ----------------
__global__ void g2a(const float* __restrict__ Wg2, const float* __restrict__ Wo2)
{
    int j = blockIdx.x * 256 + threadIdx.x;     // 2048
    const float* y = &g_YO1[j * 32];
    float z0 = 0.f, z1 = 0.f, z2 = 0.f, z3 = 0.f;
#pragma unroll
    for (int k = 0; k < 16; k++) {
        z0 = fmaf(y[k], Wg2[k * 2 + 0], z0);
        z1 = fmaf(y[k], Wg2[k * 2 + 1], z1);
        z2 = fmaf(y[16 + k], Wo2[k * 2 + 0], z2);
        z3 = fmaf(y[16 + k], Wo2[k * 2 + 1], z3);
    }
    g_Z[j] = make_float4(z0, z1, z2, z3);
}

// ---------------- G2b: a0 @ Z + bias, log_softmax / leaky ----------------
__global__ void __launch_bounds__(256) g2b(const float* __restrict__ adj,
                                           const float* __restrict__ bg2,
                                           const float* __restrict__ bo2,
                                           float* __restrict__ out)
{
    int warp = threadIdx.x >> 5, lane = threadIdx.x & 31;
    int r = blockIdx.x * 8 + warp;
    float a0 = 0.f, a1 = 0.f, a2 = 0.f, a3 = 0.f;
    for (int q = 0; q < 64; q++) {
        int k = q * 32 + lane;
        float av = adj[(size_t)r * E + k];
        float4 z = g_Z[k];
        a0 = fmaf(av, z.x, a0);
        a1 = fmaf(av, z.y, a1);
        a2 = fmaf(av, z.z, a2);
        a3 = fmaf(av, z.w, a3);
    }
    for (int off = 16; off; off >>= 1) {
        a0 += __shfl_down_sync(0xffffffffu, a0, off);
        a1 += __shfl_down_sync(0xffffffffu, a1, off);
        a2 += __shfl_down_sync(0xffffffffu, a2, off);
        a3 += __shfl_down_sync(0xffffffffu, a3, off);
    }
    if (lane == 0) {
        float y0 = a0 + bg2[0], y1 = a1 + bg2[1];
        float m = fmaxf(y0, y1);
        float l = m + logf(expf(y0 - m) + expf(y1 - m));
        out[r * 2 + 0] = y0 - l;
        out[r * 2 + 1] = y1 - l;
        float o0 = a2 + bo2[0], o1 = a3 + bo2[1];
        out[2 * E + r * 2 + 0] = o0 > 0.f ? o0 : 0.01f * o0;
        out[2 * E + r * 2 + 1] = o1 > 0.f ? o1 : 0.01f * o1;
    }
}

// ---------------- launch ----------------
extern "C" void kernel_launch(void* const* d_in, const int* in_sizes, int n_in,
                              void* d_out, int out_size)
{
    (void)in_sizes; (void)n_in; (void)out_size;
    const float* node = (const float*)d_in[0];
    const float* uv   = (const float*)d_in[1];
    const float* adj  = (const float*)d_in[2];   // batch 0 = first E*E floats
    const float* Wt1  = (const float*)d_in[3];
    const float* at1  = (const float*)d_in[4];
    const float* Wt2  = (const float*)d_in[5];
    const float* at2  = (const float*)d_in[6];
    const float* Wg1  = (const float*)d_in[7];
    const float* bg1  = (const float*)d_in[8];
    const float* Wg2  = (const float*)d_in[9];
    const float* bg2  = (const float*)d_in[10];
    const float* Wo1  = (const float*)d_in[11];
    const float* bo1  = (const float*)d_in[12];
    const float* Wo2  = (const float*)d_in[13];
    const float* bo2  = (const float*)d_in[14];
    float* out = (float*)d_out;

    k1_prep<<<dim3(8, 3), 256>>>(node, Wt1, at1, 0);
    k1_prep<<<dim3(8, 3), 256>>>(uv,   Wt2, at2, 3);
    k2_rowsum<<<256, 256>>>(adj);
    k3_att<<<dim3(32, NSLAB), 192>>>(adj);      // 4th launch -> profiled
    k4_reduce<<<288, 256>>>();
    k5_xw<<<256, 256>>>(Wg1, Wo1);
    g1_gemm<<<dim3(32, 8), 256>>>(adj);
    g1_reduce<<<256, 256>>>(bg1, bo1);
    g2a<<<8, 256>>>(Wg2, Wo2);
    g2b<<<256, 256>>>(adj, bg2, bo2, out);
}

// round 5
// speedup vs baseline: 1.1794x; 1.0604x over previous
#include <cuda_runtime.h>
#include <math.h>

#define E 2048
#define NSLAB 32
#define SLABSZ 64

typedef unsigned long long ull;

// ---------------- static scratch ----------------
__device__ ull    g_PN[6 * E];            // pack(exp(e2), exp(.2 e2)) per node-as-j
__device__ ull    g_m1[6 * E];            // pack(exp(e1), exp(.2 e1)) per node-as-i
__device__ ull    g_m2[6 * E];            // pack(P1/R, N1/R)
__device__ ull    g_h01[6 * E];
__device__ ull    g_h23[6 * E];
__device__ ull    g_h45[6 * E];
__device__ float  g_part[NSLAB * 36 * E]; // [slab][cd][j]
__device__ float  g_XW[E * 32];
__device__ float  g_G1p[8 * E * 32];
__device__ float4 g_Z[E];

// ---------------- packed f32x2 helpers ----------------
__device__ __forceinline__ ull pack2(float x, float y) {
    ull r; asm("mov.b64 %0, {%1, %2};" : "=l"(r) : "f"(x), "f"(y)); return r;
}
__device__ __forceinline__ float2 unpack2(ull v) {
    float2 r; asm("mov.b64 {%0, %1}, %2;" : "=f"(r.x), "=f"(r.y) : "l"(v)); return r;
}
__device__ __forceinline__ void ffma2(ull& d, ull a, ull b) {
    asm("fma.rn.f32x2 %0, %1, %2, %0;" : "+l"(d) : "l"(a), "l"(b));
}
__device__ __forceinline__ ull mul2(ull a, ull b) {
    ull r; asm("mul.rn.f32x2 %0, %1, %2;" : "=l"(r) : "l"(a), "l"(b)); return r;
}

// ---------------- K1: per-node h + factor pairs (one gat) ----------------
__global__ void k1_prep(const float* __restrict__ x, const float* __restrict__ Wt,
                        const float* __restrict__ at, int cbase)
{
    int t = blockIdx.y;
    int c = cbase + t;
    int i = blockIdx.x * 256 + threadIdx.x;
    __shared__ float sW[192];
    __shared__ float sa[12];
    if (threadIdx.x < 192) sW[threadIdx.x] = Wt[t * 192 + threadIdx.x];
    if (threadIdx.x < 12)  sa[threadIdx.x] = at[t * 12 + threadIdx.x];
    __syncthreads();

    const float* xr = x + i * 32;   // batch 0
    float h[6] = {0.f, 0.f, 0.f, 0.f, 0.f, 0.f};
#pragma unroll
    for (int k = 0; k < 32; k++) {
        float xk = xr[k];
#pragma unroll
        for (int d = 0; d < 6; d++) h[d] = fmaf(xk, sW[k * 6 + d], h[d]);
    }
    float e1 = 0.f, e2 = 0.f;
#pragma unroll
    for (int d = 0; d < 6; d++) {
        e1 = fmaf(h[d], sa[d], e1);
        e2 = fmaf(h[d], sa[6 + d], e2);
    }
    int gi = c * E + i;
    g_m1[gi] = pack2(__expf(e1), __expf(0.2f * e1));
    g_PN[gi] = pack2(__expf(e2), __expf(0.2f * e2));
    g_h01[gi] = pack2(h[0], h[1]);
    g_h23[gi] = pack2(h[2], h[3]);
    g_h45[gi] = pack2(h[4], h[5]);
}

// ---------------- K2: softmax row denominators (warp per row) ----------------
// exp(leaky(e1+e2)) = max(P1*P2, N1*N2)
__global__ void __launch_bounds__(256) k2_rowsum(const float* __restrict__ adj)
{
    int warp = threadIdx.x >> 5, lane = threadIdx.x & 31;
    int r = blockIdx.x * 8 + warp;

    ull mk[6]; float acc[6];
#pragma unroll
    for (int c = 0; c < 6; c++) { mk[c] = g_m1[c * E + r]; acc[c] = 0.f; }

    const float* arow = &adj[(size_t)r * E];
    for (int it = 0; it < 16; it++) {
        int j = it * 128 + lane * 4;
        float4 av = *(const float4*)&arow[j];
#pragma unroll
        for (int c = 0; c < 6; c++) {
            ulonglong2 pn01 = *(const ulonglong2*)&g_PN[c * E + j];
            ulonglong2 pn23 = *(const ulonglong2*)&g_PN[c * E + j + 2];
            float2 t;
            t = unpack2(mul2(mk[c], pn01.x)); acc[c] = fmaf(av.x, fmaxf(t.x, t.y), acc[c]);
            t = unpack2(mul2(mk[c], pn01.y)); acc[c] = fmaf(av.y, fmaxf(t.x, t.y), acc[c]);
            t = unpack2(mul2(mk[c], pn23.x)); acc[c] = fmaf(av.z, fmaxf(t.x, t.y), acc[c]);
            t = unpack2(mul2(mk[c], pn23.y)); acc[c] = fmaf(av.w, fmaxf(t.x, t.y), acc[c]);
        }
    }

#pragma unroll
    for (int c = 0; c < 6; c++) {
        float v = acc[c];
        for (int off = 16; off; off >>= 1) v += __shfl_down_sync(0xffffffffu, v, off);
        if (lane == 0) {
            float inv = 1.0f / v;
            float2 m = unpack2(mk[c]);
            g_m2[c * E + r] = pack2(m.x * inv, m.y * inv);
        }
    }
}

// ---------------- K3: attention-weighted aggregation ----------------
// 192 thr = 6 warps (warp=combo); lane owns 4 j; block = 128 j x 64 i
__global__ void __launch_bounds__(192, 4) k3_att(const float* __restrict__ adj)
{
    __shared__ ull s_pk[6][SLABSZ], s_h01[6][SLABSZ], s_h23[6][SLABSZ], s_h45[6][SLABSZ];

    int tid = threadIdx.x;
    int c   = tid >> 5;
    int lane = tid & 31;
    int j0  = blockIdx.x * 128 + lane * 4;
    int ib  = blockIdx.y * SLABSZ;

    ull PN[4];
#pragma unroll
    for (int q = 0; q < 4; q++) PN[q] = g_PN[c * E + j0 + q];

    ull acc[12];
#pragma unroll
    for (int q = 0; q < 12; q++) acc[q] = 0;

    for (int t = tid; t < 6 * SLABSZ; t += 192) {
        int cc = t >> 6, ii = t & 63;
        int gi = cc * E + ib + ii;
        s_pk[cc][ii]  = g_m2[gi];
        s_h01[cc][ii] = g_h01[gi];
        s_h23[cc][ii] = g_h23[gi];
        s_h45[cc][ii] = g_h45[gi];
    }
    __syncthreads();

#pragma unroll 1
    for (int ii = 0; ii < SLABSZ; ii += 4) {
        float4 av[4];
#pragma unroll
        for (int u = 0; u < 4; u++)
            av[u] = *(const float4*)&adj[(size_t)(ib + ii + u) * E + j0];
#pragma unroll
        for (int u = 0; u < 4; u++) {
            ull pk  = s_pk[c][ii + u];
            ull h01 = s_h01[c][ii + u];
            ull h23 = s_h23[c][ii + u];
            ull h45 = s_h45[c][ii + u];
            const float* af = (const float*)&av[u];
#pragma unroll
            for (int q = 0; q < 4; q++) {
                float2 t = unpack2(mul2(pk, PN[q]));
                float w = fmaxf(t.x, t.y) * af[q];
                ull wp = pack2(w, w);
                ffma2(acc[q * 3 + 0], wp, h01);
                ffma2(acc[q * 3 + 1], wp, h23);
                ffma2(acc[q * 3 + 2], wp, h45);
            }
        }
    }

    int base = blockIdx.y * 36 + c * 6;
#pragma unroll
    for (int p = 0; p < 3; p++) {
        float2 t0 = unpack2(acc[p]), t1 = unpack2(acc[3 + p]);
        float2 t2 = unpack2(acc[6 + p]), t3 = unpack2(acc[9 + p]);
        *(float4*)&g_part[(size_t)(base + 2 * p) * E + j0] =
            make_float4(t0.x, t1.x, t2.x, t3.x);
        *(float4*)&g_part[(size_t)(base + 2 * p + 1) * E + j0] =
            make_float4(t0.y, t1.y, t2.y, t3.y);
    }
}

// ---------------- K45: slab-reduce + ELU + XW (fused) ----------------
__global__ void __launch_bounds__(256) k45(const float* __restrict__ Wg1,
                                           const float* __restrict__ Wo1)
{
    __shared__ float sh[36][33];
    __shared__ float sW[2][288];
    int tid = threadIdx.x;
    int j0 = blockIdx.x * 32;

    for (int t = tid; t < 288; t += 256) {
        sW[0][t] = Wg1[t];
        sW[1][t] = Wo1[t];
    }
    for (int t = tid; t < 36 * 32; t += 256) {
        int cd = t >> 5, jj = t & 31;
        int j = j0 + jj;
        float s = 0.f;
#pragma unroll
        for (int sl = 0; sl < NSLAB; sl++) s += g_part[(size_t)(sl * 36 + cd) * E + j];
        sh[cd][jj] = s > 0.f ? s : expm1f(s);
    }
    __syncthreads();

    for (int o = tid; o < 1024; o += 256) {
        int c = o >> 5, jj = o & 31;
        int g = c >> 4, cc = c & 15;
        float s = 0.f;
#pragma unroll
        for (int k = 0; k < 18; k++)
            s = fmaf(sh[g * 18 + k][jj], sW[g][k * 16 + cc], s);
        g_XW[(j0 + jj) * 32 + c] = s;
    }
}

// ---------------- G1: a0 @ XW (tiled, k-split) ----------------
__global__ void __launch_bounds__(256) g1_gemm(const float* __restrict__ adj)
{
    __shared__ float As[64][33];
    __shared__ float Bs[32][32];
    int r0 = blockIdx.x * 64, k0 = blockIdx.y * 256;
    int rl = threadIdx.x >> 2, cg = (threadIdx.x & 3) * 8;
    int kc = threadIdx.x & 31, rr = threadIdx.x >> 5;

    float acc[8];
#pragma unroll
    for (int u = 0; u < 8; u++) acc[u] = 0.f;

    for (int kt = 0; kt < 8; kt++) {
        int kb = k0 + kt * 32;
#pragma unroll
        for (int p = 0; p < 8; p++)
            As[rr + p * 8][kc] = adj[(size_t)(r0 + rr + p * 8) * E + kb + kc];
#pragma unroll
        for (int p = 0; p < 4; p++)
            Bs[rr + p * 8][kc] = g_XW[(kb + rr + p * 8) * 32 + kc];
        __syncthreads();
#pragma unroll
        for (int kk = 0; kk < 32; kk++) {
            float a = As[rl][kk];
            const float4* b = (const float4*)&Bs[kk][cg];
            float4 b0 = b[0], b1 = b[1];
            acc[0] = fmaf(a, b0.x, acc[0]);
            acc[1] = fmaf(a, b0.y, acc[1]);
            acc[2] = fmaf(a, b0.z, acc[2]);
            acc[3] = fmaf(a, b0.w, acc[3]);
            acc[4] = fmaf(a, b1.x, acc[4]);
            acc[5] = fmaf(a, b1.y, acc[5]);
            acc[6] = fmaf(a, b1.z, acc[6]);
            acc[7] = fmaf(a, b1.w, acc[7]);
        }
        __syncthreads();
    }
    float* dst = &g_G1p[((size_t)blockIdx.y * E + r0 + rl) * 32 + cg];
    ((float4*)dst)[0] = make_float4(acc[0], acc[1], acc[2], acc[3]);
    ((float4*)dst)[1] = make_float4(acc[4], acc[5], acc[6], acc[7]);
}

// ---------------- G12: k-slice reduce + bias + relu + second-layer weights ----------------
__global__ void __launch_bounds__(256) g12(const float* __restrict__ bg1,
                                           const float* __restrict__ bo1,
                                           const float* __restrict__ Wg2,
                                           const float* __restrict__ Wo2)
{
    int j = blockIdx.x * 256 + threadIdx.x;
    float y[32];
#pragma unroll
    for (int c4 = 0; c4 < 8; c4++) {
        float4 s = make_float4(0.f, 0.f, 0.f, 0.f);
#pragma unroll
        for (int ks = 0; ks < 8; ks++) {
            float4 v = *(const float4*)&g_G1p[((size_t)ks * E + j) * 32 + c4 * 4];
            s.x += v.x; s.y += v.y; s.z += v.z; s.w += v.w;
        }
        y[c4 * 4 + 0] = s.x; y[c4 * 4 + 1] = s.y;
        y[c4 * 4 + 2] = s.z; y[c4 * 4 + 3] = s.w;
    }
#pragma unroll
    for (int c = 0; c < 16; c++) {
        float a = y[c] + __ldg(&bg1[c]);
        y[c] = a > 0.f ? a : 0.f;
        float b = y[16 + c] + __ldg(&bo1[c]);
        y[16 + c] = b > 0.f ? b : 0.f;
    }
    float z0 = 0.f, z1 = 0.f, z2 = 0.f, z3 = 0.f;
#pragma unroll
    for (int k = 0; k < 16; k++) {
        z0 = fmaf(y[k], __ldg(&Wg2[k * 2 + 0]), z0);
        z1 = fmaf(y[k], __ldg(&Wg2[k * 2 + 1]), z1);
        z2 = fmaf(y[16 + k], __ldg(&Wo2[k * 2 + 0]), z2);
        z3 = fmaf(y[16 + k], __ldg(&Wo2[k * 2 + 1]), z3);
    }
    g_Z[j] = make_float4(z0, z1, z2, z3);
}

// ---------------- G2b: a0 @ Z + bias, log_softmax / leaky ----------------
__global__ void __launch_bounds__(256) g2b(const float* __restrict__ adj,
                                           const float* __restrict__ bg2,
                                           const float* __restrict__ bo2,
                                           float* __restrict__ out)
{
    int warp = threadIdx.x >> 5, lane = threadIdx.x & 31;
    int r = blockIdx.x * 8 + warp;
    float a0 = 0.f, a1 = 0.f, a2 = 0.f, a3 = 0.f;
    for (int q = 0; q < 64; q++) {
        int k = q * 32 + lane;
        float av = adj[(size_t)r * E + k];
        float4 z = g_Z[k];
        a0 = fmaf(av, z.x, a0);
        a1 = fmaf(av, z.y, a1);
        a2 = fmaf(av, z.z, a2);
        a3 = fmaf(av, z.w, a3);
    }
    for (int off = 16; off; off >>= 1) {
        a0 += __shfl_down_sync(0xffffffffu, a0, off);
        a1 += __shfl_down_sync(0xffffffffu, a1, off);
        a2 += __shfl_down_sync(0xffffffffu, a2, off);
        a3 += __shfl_down_sync(0xffffffffu, a3, off);
    }
    if (lane == 0) {
        float y0 = a0 + bg2[0], y1 = a1 + bg2[1];
        float m = fmaxf(y0, y1);
        float l = m + logf(expf(y0 - m) + expf(y1 - m));
        out[r * 2 + 0] = y0 - l;
        out[r * 2 + 1] = y1 - l;
        float o0 = a2 + bo2[0], o1 = a3 + bo2[1];
        out[2 * E + r * 2 + 0] = o0 > 0.f ? o0 : 0.01f * o0;
        out[2 * E + r * 2 + 1] = o1 > 0.f ? o1 : 0.01f * o1;
    }
}

// ---------------- launch ----------------
extern "C" void kernel_launch(void* const* d_in, const int* in_sizes, int n_in,
                              void* d_out, int out_size)
{
    (void)in_sizes; (void)n_in; (void)out_size;
    const float* node = (const float*)d_in[0];
    const float* uv   = (const float*)d_in[1];
    const float* adj  = (const float*)d_in[2];   // batch 0 = first E*E floats
    const float* Wt1  = (const float*)d_in[3];
    const float* at1  = (const float*)d_in[4];
    const float* Wt2  = (const float*)d_in[5];
    const float* at2  = (const float*)d_in[6];
    const float* Wg1  = (const float*)d_in[7];
    const float* bg1  = (const float*)d_in[8];
    const float* Wg2  = (const float*)d_in[9];
    const float* bg2  = (const float*)d_in[10];
    const float* Wo1  = (const float*)d_in[11];
    const float* bo1  = (const float*)d_in[12];
    const float* Wo2  = (const float*)d_in[13];
    const float* bo2  = (const float*)d_in[14];
    float* out = (float*)d_out;

    k1_prep<<<dim3(8, 3), 256>>>(node, Wt1, at1, 0);
    k1_prep<<<dim3(8, 3), 256>>>(uv,   Wt2, at2, 3);
    k2_rowsum<<<256, 256>>>(adj);
    k3_att<<<dim3(16, NSLAB), 192>>>(adj);      // 4th launch -> profiled
    k45<<<64, 256>>>(Wg1, Wo1);
    g1_gemm<<<dim3(32, 8), 256>>>(adj);
    g12<<<8, 256>>>(bg1, bo1, Wg2, Wo2);
    g2b<<<256, 256>>>(adj, bg2, bo2, out);
}